// round 13
// baseline (speedup 1.0000x reference)
#include <cuda_runtime.h>
#include <cuda_bf16.h>
#include <cstdint>

#define TOKENS 2048   // B*T
#define BATCH  4
#define SEQ    512
#define HID    2048
#define VOCAB  32000

#define BM 128
#define BN 128
#define BK 32
#define LDS_PAD 40    // halves per smem row (32 + 8 pad) -> conflict-free ldmatrix

// scratch (allocation-free rule: __device__ globals)
__device__ float g_sumexp[2 * TOKENS];
__device__ float g_tgt[2 * TOKENS];

// ---------------------------------------------------------------------------
__global__ void k_init() {
    int i = blockIdx.x * blockDim.x + threadIdx.x;
    if (i < 2 * TOKENS) g_sumexp[i] = 0.f;
}

// ---------------------------------------------------------------------------
// Target logits: one warp per (model, token). Dot(x[m], W[y[m]]) over H=2048.
__global__ void k_target(const float* __restrict__ x, const float* __restrict__ rx,
                         const float* __restrict__ W, const float* __restrict__ rW,
                         const int* __restrict__ y) {
    int warp = (blockIdx.x * blockDim.x + threadIdx.x) >> 5;
    int lane = threadIdx.x & 31;
    if (warp >= 2 * TOKENS) return;
    int model = warp >> 11;            // TOKENS = 2^11
    int m     = warp & (TOKENS - 1);

    // int64-vs-int32 detection: y[0]=y[1]=-100 guaranteed by reference masking.
    // int64 layout -> int32 view [1] is the high word of -100 == -1.
    bool y64  = (y[1] == -1);
    int label = y[y64 ? 2 * m : m];

    float v = 0.f;
    if (label >= 0) {
        const float4* a4 = (const float4*)((model ? rx : x) + (size_t)m * HID);
        const float4* b4 = (const float4*)((model ? rW : W) + (size_t)label * HID);
        #pragma unroll 4
        for (int i = lane; i < HID / 4; i += 32) {
            float4 av = a4[i], bv = b4[i];
            v += av.x * bv.x + av.y * bv.y + av.z * bv.z + av.w * bv.w;
        }
    }
    #pragma unroll
    for (int s = 16; s; s >>= 1) v += __shfl_xor_sync(0xffffffffu, v, s);
    if (lane == 0) g_tgt[warp] = v;
}

// ---------------------------------------------------------------------------
__device__ __forceinline__ void ldsm_x4(uint32_t& r0, uint32_t& r1, uint32_t& r2,
                                        uint32_t& r3, uint32_t addr) {
    asm volatile("ldmatrix.sync.aligned.m8n8.x4.shared.b16 {%0,%1,%2,%3}, [%4];\n"
                 : "=r"(r0), "=r"(r1), "=r"(r2), "=r"(r3) : "r"(addr));
}
__device__ __forceinline__ void ldsm_x2(uint32_t& r0, uint32_t& r1, uint32_t addr) {
    asm volatile("ldmatrix.sync.aligned.m8n8.x2.shared.b16 {%0,%1}, [%2];\n"
                 : "=r"(r0), "=r"(r1) : "r"(addr));
}
__device__ __forceinline__ void mma16816(float* c, const uint32_t* a, const uint32_t* b) {
    asm volatile(
        "mma.sync.aligned.m16n8k16.row.col.f32.bf16.bf16.f32 "
        "{%0,%1,%2,%3}, {%4,%5,%6,%7}, {%8,%9}, {%0,%1,%2,%3};\n"
        : "+f"(c[0]), "+f"(c[1]), "+f"(c[2]), "+f"(c[3])
        : "r"(a[0]), "r"(a[1]), "r"(a[2]), "r"(a[3]), "r"(b[0]), "r"(b[1]));
}
__device__ __forceinline__ uint2 pack_bf16x4(float4 v) {
    __nv_bfloat162 lo = __floats2bfloat162_rn(v.x, v.y);
    __nv_bfloat162 hi = __floats2bfloat162_rn(v.z, v.w);
    uint2 r;
    r.x = *(uint32_t*)&lo;
    r.y = *(uint32_t*)&hi;
    return r;
}

// GEMM + online exp-sum epilogue.
// grid = (M/BM fastest, N/BN, 2 models); 256 threads = 8 warps in 2(M)x4(N),
// each warp owns a 64x32 output tile via 4x4 m16n8k16 fragments.
__global__ __launch_bounds__(256)
void k_gemm(const float* __restrict__ x, const float* __restrict__ rx,
            const float* __restrict__ W, const float* __restrict__ rW) {
    const int model = blockIdx.z;
    const float* A = model ? rx : x;
    const float* B = model ? rW : W;
    const int bm = blockIdx.x;
    const int bn = blockIdx.y;

    __shared__ __nv_bfloat16 As[2][BM * LDS_PAD];
    __shared__ __nv_bfloat16 Bs[2][BN * LDS_PAD];

    const int tid  = threadIdx.x;
    const int lane = tid & 31;
    const int w    = tid >> 5;
    const int wm   = w >> 2;   // 0..1
    const int wn   = w & 3;    // 0..3

    // Global loads: thread t covers rows (t>>3)+j*32, float4 col (t&7).
    // Per j a warp reads 4 rows x 8 lanes x 16B = 4 fully-coalesced 128B lines.
    const int glr = tid >> 3;        // 0..31
    const int glc = tid & 7;         // float4 index in the 32-float K-chunk
    const float* Ag = A + (size_t)(bm * BM + glr) * HID + glc * 4;
    const float* Bg = B + (size_t)(bn * BN + glr) * HID + glc * 4;

    float acc[4][4][4];
    #pragma unroll
    for (int i = 0; i < 4; i++)
        #pragma unroll
        for (int j = 0; j < 4; j++)
            #pragma unroll
            for (int e = 0; e < 4; e++) acc[i][j][e] = 0.f;

    uint32_t asb[2], bsb[2];
    asb[0] = (uint32_t)__cvta_generic_to_shared(&As[0][0]);
    asb[1] = (uint32_t)__cvta_generic_to_shared(&As[1][0]);
    bsb[0] = (uint32_t)__cvta_generic_to_shared(&Bs[0][0]);
    bsb[1] = (uint32_t)__cvta_generic_to_shared(&Bs[1][0]);

    float4 ra[4], rb[4];
    #pragma unroll
    for (int j = 0; j < 4; j++) {
        ra[j] = *(const float4*)(Ag + (size_t)j * 32 * HID);
        rb[j] = *(const float4*)(Bg + (size_t)j * 32 * HID);
    }
    // stage tile 0 -> buffer 0
    #pragma unroll
    for (int j = 0; j < 4; j++) {
        *(uint2*)&As[0][(glr + j * 32) * LDS_PAD + glc * 4] = pack_bf16x4(ra[j]);
        *(uint2*)&Bs[0][(glr + j * 32) * LDS_PAD + glc * 4] = pack_bf16x4(rb[j]);
    }

    const int KIT = HID / BK;   // 64
    for (int it = 0; it < KIT; ++it) {
        __syncthreads();                       // staged buffer (it&1) visible
        const int buf = it & 1;

        if (it + 1 < KIT) {
            const int ko = (it + 1) * BK;
            #pragma unroll
            for (int j = 0; j < 4; j++) {
                ra[j] = *(const float4*)(Ag + (size_t)j * 32 * HID + ko);
                rb[j] = *(const float4*)(Bg + (size_t)j * 32 * HID + ko);
            }
        }

        #pragma unroll
        for (int ks = 0; ks < 2; ks++) {
            uint32_t af[4][4];
            #pragma unroll
            for (int mi = 0; mi < 4; mi++) {
                int row = wm * 64 + mi * 16 + ((lane >> 3) & 1) * 8 + (lane & 7);
                int col = ks * 16 + (lane >> 4) * 8;
                ldsm_x4(af[mi][0], af[mi][1], af[mi][2], af[mi][3],
                        asb[buf] + (uint32_t)(row * LDS_PAD + col) * 2);
            }
            uint32_t bfrag[4][2];
            #pragma unroll
            for (int ni = 0; ni < 4; ni++) {
                int row = wn * 32 + ni * 8 + (lane & 7);
                int col = ks * 16 + ((lane >> 3) & 1) * 8;
                ldsm_x2(bfrag[ni][0], bfrag[ni][1],
                        bsb[buf] + (uint32_t)(row * LDS_PAD + col) * 2);
            }
            #pragma unroll
            for (int mi = 0; mi < 4; mi++)
                #pragma unroll
                for (int ni = 0; ni < 4; ni++)
                    mma16816(acc[mi][ni], af[mi], bfrag[ni]);
        }

        __syncthreads();                       // everyone done with buf^1 reads
        if (it + 1 < KIT) {
            const int nb = (it + 1) & 1;
            #pragma unroll
            for (int j = 0; j < 4; j++) {
                *(uint2*)&As[nb][(glr + j * 32) * LDS_PAD + glc * 4] = pack_bf16x4(ra[j]);
                *(uint2*)&Bs[nb][(glr + j * 32) * LDS_PAD + glc * 4] = pack_bf16x4(rb[j]);
            }
        }
    }

    // Epilogue: exp + row-sum over this block's 128 vocab columns.
    // c0,c1 -> row lane>>2 ; c2,c3 -> row (lane>>2)+8 ; quad lanes share a row.
    const int rowbase = bm * BM + wm * 64;
    #pragma unroll
    for (int mi = 0; mi < 4; mi++) {
        float s0 = 0.f, s1 = 0.f;
        #pragma unroll
        for (int ni = 0; ni < 4; ni++) {
            s0 += __expf(acc[mi][ni][0]) + __expf(acc[mi][ni][1]);
            s1 += __expf(acc[mi][ni][2]) + __expf(acc[mi][ni][3]);
        }
        s0 += __shfl_xor_sync(0xffffffffu, s0, 1);
        s0 += __shfl_xor_sync(0xffffffffu, s0, 2);
        s1 += __shfl_xor_sync(0xffffffffu, s1, 1);
        s1 += __shfl_xor_sync(0xffffffffu, s1, 2);
        if ((lane & 3) == 0) {
            int r = rowbase + mi * 16 + (lane >> 2);
            atomicAdd(&g_sumexp[model * TOKENS + r],     s0);
            atomicAdd(&g_sumexp[model * TOKENS + r + 8], s1);
        }
    }
}

// ---------------------------------------------------------------------------
__global__ void k_final(const int* __restrict__ y,
                        const unsigned char* __restrict__ pl_raw,
                        float* __restrict__ out) {
    __shared__ float pol[BATCH], ref[BATCH], cnt[BATCH];
    int tid = threadIdx.x;
    if (tid < BATCH) { pol[tid] = 0.f; ref[tid] = 0.f; cnt[tid] = 0.f; }
    __syncthreads();

    bool y64 = (y[1] == -1);
    for (int m = tid; m < TOKENS; m += blockDim.x) {
        int label = y[y64 ? 2 * m : m];
        if (label >= 0) {
            int b = m / SEQ;
            float p = g_tgt[m]          - logf(g_sumexp[m]);
            float r = g_tgt[TOKENS + m] - logf(g_sumexp[TOKENS + m]);
            atomicAdd(&pol[b], p);
            atomicAdd(&ref[b], r);
            atomicAdd(&cnt[b], 1.f);
        }
    }
    __syncthreads();

    if (tid == 0) {
        // preference_labels dtype hedge: int32 / float32 / byte encodings.
        const uint32_t* pi = (const uint32_t*)pl_raw;
        uint32_t i0 = pi[0], i1 = pi[1], i2 = pi[2], i3 = pi[3];
        bool lab[BATCH];
        bool int_mode = (i0 <= 1u) && (i1 <= 1u) && (i2 <= 1u) && (i3 <= 1u);
        bool flt_mode = !int_mode &&
            (i0 == 0u || i0 == 0x3F800000u) && (i1 == 0u || i1 == 0x3F800000u) &&
            (i2 == 0u || i2 == 0x3F800000u) && (i3 == 0u || i3 == 0x3F800000u);
        if (int_mode) {
            lab[0] = i0 != 0u; lab[1] = i1 != 0u; lab[2] = i2 != 0u; lab[3] = i3 != 0u;
        } else if (flt_mode) {
            lab[0] = i0 != 0u; lab[1] = i1 != 0u; lab[2] = i2 != 0u; lab[3] = i3 != 0u;
        } else {
            #pragma unroll
            for (int b = 0; b < BATCH; b++) lab[b] = pl_raw[b] != 0;
        }

        float loss = 0.f;
        #pragma unroll
        for (int b = 0; b < BATCH; b++) {
            float lp = pol[b] / cnt[b];
            float lr = ref[b] / cnt[b];
            float mult = lab[b] ? 1.f : -1.f;
            float z = 0.1f * (lp - lr) * mult;
            float s = 1.f / (1.f + expf(-z));
            loss += 1.f - s;
        }
        out[0] = loss / (float)BATCH;
    }
}

// ---------------------------------------------------------------------------
extern "C" void kernel_launch(void* const* d_in, const int* in_sizes, int n_in,
                              void* d_out, int out_size) {
    (void)in_sizes; (void)n_in; (void)out_size;
    const float*         x  = (const float*)d_in[0];
    const float*         rx = (const float*)d_in[1];
    const int*           y  = (const int*)d_in[2];
    const unsigned char* pl = (const unsigned char*)d_in[3];
    const float*         W  = (const float*)d_in[4];
    const float*         rW = (const float*)d_in[5];
    float* out = (float*)d_out;

    k_init<<<16, 256>>>();
    k_target<<<(2 * TOKENS * 32) / 256, 256>>>(x, rx, W, rW, y);
    dim3 grid(TOKENS / BM, VOCAB / BN, 2);   // M fastest -> W tile L2 reuse
    k_gemm<<<grid, 256>>>(x, rx, W, rW);
    k_final<<<1, 256>>>(y, pl, out);
}

// round 14
// speedup vs baseline: 1.0021x; 1.0021x over previous
#include <cuda_runtime.h>
#include <cuda_bf16.h>
#include <cstdint>

#define TOKENS 2048   // B*T
#define BATCH  4
#define SEQ    512
#define HID    2048
#define VOCAB  32000

#define BM 128
#define BN 128
#define BK 32
#define LDS_PAD 40    // halves per smem row (32 + 8 pad) -> conflict-free ldmatrix

// scratch (allocation-free rule: __device__ globals)
__device__ float g_sumexp[2 * TOKENS];
__device__ float g_tgt[2 * TOKENS];

// ---------------------------------------------------------------------------
__global__ void k_init() {
    int i = blockIdx.x * blockDim.x + threadIdx.x;
    if (i < 2 * TOKENS) g_sumexp[i] = 0.f;
}

// ---------------------------------------------------------------------------
// Target logits: one warp per (model, token). Dot(x[m], W[y[m]]) over H=2048.
__global__ void k_target(const float* __restrict__ x, const float* __restrict__ rx,
                         const float* __restrict__ W, const float* __restrict__ rW,
                         const int* __restrict__ y) {
    int warp = (blockIdx.x * blockDim.x + threadIdx.x) >> 5;
    int lane = threadIdx.x & 31;
    if (warp >= 2 * TOKENS) return;
    int model = warp >> 11;            // TOKENS = 2^11
    int m     = warp & (TOKENS - 1);

    // int64-vs-int32 detection: y[0]=y[1]=-100 guaranteed by reference masking.
    // int64 layout -> int32 view [1] is the high word of -100 == -1.
    bool y64  = (y[1] == -1);
    int label = y[y64 ? 2 * m : m];

    float v = 0.f;
    if (label >= 0) {
        const float4* a4 = (const float4*)((model ? rx : x) + (size_t)m * HID);
        const float4* b4 = (const float4*)((model ? rW : W) + (size_t)label * HID);
        #pragma unroll 4
        for (int i = lane; i < HID / 4; i += 32) {
            float4 av = a4[i], bv = b4[i];
            v += av.x * bv.x + av.y * bv.y + av.z * bv.z + av.w * bv.w;
        }
    }
    #pragma unroll
    for (int s = 16; s; s >>= 1) v += __shfl_xor_sync(0xffffffffu, v, s);
    if (lane == 0) g_tgt[warp] = v;
}

// ---------------------------------------------------------------------------
__device__ __forceinline__ void ldsm_x4(uint32_t& r0, uint32_t& r1, uint32_t& r2,
                                        uint32_t& r3, uint32_t addr) {
    asm volatile("ldmatrix.sync.aligned.m8n8.x4.shared.b16 {%0,%1,%2,%3}, [%4];\n"
                 : "=r"(r0), "=r"(r1), "=r"(r2), "=r"(r3) : "r"(addr));
}
__device__ __forceinline__ void ldsm_x2(uint32_t& r0, uint32_t& r1, uint32_t addr) {
    asm volatile("ldmatrix.sync.aligned.m8n8.x2.shared.b16 {%0,%1}, [%2];\n"
                 : "=r"(r0), "=r"(r1) : "r"(addr));
}
__device__ __forceinline__ void mma16816(float* c, const uint32_t* a, const uint32_t* b) {
    asm volatile(
        "mma.sync.aligned.m16n8k16.row.col.f32.bf16.bf16.f32 "
        "{%0,%1,%2,%3}, {%4,%5,%6,%7}, {%8,%9}, {%0,%1,%2,%3};\n"
        : "+f"(c[0]), "+f"(c[1]), "+f"(c[2]), "+f"(c[3])
        : "r"(a[0]), "r"(a[1]), "r"(a[2]), "r"(a[3]), "r"(b[0]), "r"(b[1]));
}
__device__ __forceinline__ uint2 pack_bf16x4(float4 v) {
    __nv_bfloat162 lo = __floats2bfloat162_rn(v.x, v.y);
    __nv_bfloat162 hi = __floats2bfloat162_rn(v.z, v.w);
    uint2 r;
    r.x = *(uint32_t*)&lo;
    r.y = *(uint32_t*)&hi;
    return r;
}

// GEMM + online exp-sum epilogue.
// grid = (M/BM fastest, N/BN, 2 models); 256 threads = 8 warps in 2(M)x4(N),
// each warp owns a 64x32 output tile via 4x4 m16n8k16 fragments.
__global__ __launch_bounds__(256)
void k_gemm(const float* __restrict__ x, const float* __restrict__ rx,
            const float* __restrict__ W, const float* __restrict__ rW) {
    const int model = blockIdx.z;
    const float* A = model ? rx : x;
    const float* B = model ? rW : W;
    const int bm = blockIdx.x;
    const int bn = blockIdx.y;

    __shared__ __nv_bfloat16 As[2][BM * LDS_PAD];
    __shared__ __nv_bfloat16 Bs[2][BN * LDS_PAD];

    const int tid  = threadIdx.x;
    const int lane = tid & 31;
    const int w    = tid >> 5;
    const int wm   = w >> 2;   // 0..1
    const int wn   = w & 3;    // 0..3

    // Global loads: thread t covers rows (t>>3)+j*32, float4 col (t&7).
    // Per j a warp reads 4 rows x 8 lanes x 16B = 4 fully-coalesced 128B lines.
    const int glr = tid >> 3;        // 0..31
    const int glc = tid & 7;         // float4 index in the 32-float K-chunk
    const float* Ag = A + (size_t)(bm * BM + glr) * HID + glc * 4;
    const float* Bg = B + (size_t)(bn * BN + glr) * HID + glc * 4;

    float acc[4][4][4];
    #pragma unroll
    for (int i = 0; i < 4; i++)
        #pragma unroll
        for (int j = 0; j < 4; j++)
            #pragma unroll
            for (int e = 0; e < 4; e++) acc[i][j][e] = 0.f;

    uint32_t asb[2], bsb[2];
    asb[0] = (uint32_t)__cvta_generic_to_shared(&As[0][0]);
    asb[1] = (uint32_t)__cvta_generic_to_shared(&As[1][0]);
    bsb[0] = (uint32_t)__cvta_generic_to_shared(&Bs[0][0]);
    bsb[1] = (uint32_t)__cvta_generic_to_shared(&Bs[1][0]);

    float4 ra[4], rb[4];
    #pragma unroll
    for (int j = 0; j < 4; j++) {
        ra[j] = *(const float4*)(Ag + (size_t)j * 32 * HID);
        rb[j] = *(const float4*)(Bg + (size_t)j * 32 * HID);
    }
    // stage tile 0 -> buffer 0
    #pragma unroll
    for (int j = 0; j < 4; j++) {
        *(uint2*)&As[0][(glr + j * 32) * LDS_PAD + glc * 4] = pack_bf16x4(ra[j]);
        *(uint2*)&Bs[0][(glr + j * 32) * LDS_PAD + glc * 4] = pack_bf16x4(rb[j]);
    }

    const int KIT = HID / BK;   // 64
    for (int it = 0; it < KIT; ++it) {
        __syncthreads();                       // staged buffer (it&1) visible
        const int buf = it & 1;

        if (it + 1 < KIT) {
            const int ko = (it + 1) * BK;
            #pragma unroll
            for (int j = 0; j < 4; j++) {
                ra[j] = *(const float4*)(Ag + (size_t)j * 32 * HID + ko);
                rb[j] = *(const float4*)(Bg + (size_t)j * 32 * HID + ko);
            }
        }

        #pragma unroll
        for (int ks = 0; ks < 2; ks++) {
            uint32_t af[4][4];
            #pragma unroll
            for (int mi = 0; mi < 4; mi++) {
                int row = wm * 64 + mi * 16 + ((lane >> 3) & 1) * 8 + (lane & 7);
                int col = ks * 16 + (lane >> 4) * 8;
                ldsm_x4(af[mi][0], af[mi][1], af[mi][2], af[mi][3],
                        asb[buf] + (uint32_t)(row * LDS_PAD + col) * 2);
            }
            uint32_t bfrag[4][2];
            #pragma unroll
            for (int ni = 0; ni < 4; ni++) {
                int row = wn * 32 + ni * 8 + (lane & 7);
                int col = ks * 16 + ((lane >> 3) & 1) * 8;
                ldsm_x2(bfrag[ni][0], bfrag[ni][1],
                        bsb[buf] + (uint32_t)(row * LDS_PAD + col) * 2);
            }
            #pragma unroll
            for (int mi = 0; mi < 4; mi++)
                #pragma unroll
                for (int ni = 0; ni < 4; ni++)
                    mma16816(acc[mi][ni], af[mi], bfrag[ni]);
        }

        __syncthreads();                       // everyone done with buf^1 reads
        if (it + 1 < KIT) {
            const int nb = (it + 1) & 1;
            #pragma unroll
            for (int j = 0; j < 4; j++) {
                *(uint2*)&As[nb][(glr + j * 32) * LDS_PAD + glc * 4] = pack_bf16x4(ra[j]);
                *(uint2*)&Bs[nb][(glr + j * 32) * LDS_PAD + glc * 4] = pack_bf16x4(rb[j]);
            }
        }
    }

    // Epilogue: exp + row-sum over this block's 128 vocab columns.
    // c0,c1 -> row lane>>2 ; c2,c3 -> row (lane>>2)+8 ; quad lanes share a row.
    const int rowbase = bm * BM + wm * 64;
    #pragma unroll
    for (int mi = 0; mi < 4; mi++) {
        float s0 = 0.f, s1 = 0.f;
        #pragma unroll
        for (int ni = 0; ni < 4; ni++) {
            s0 += __expf(acc[mi][ni][0]) + __expf(acc[mi][ni][1]);
            s1 += __expf(acc[mi][ni][2]) + __expf(acc[mi][ni][3]);
        }
        s0 += __shfl_xor_sync(0xffffffffu, s0, 1);
        s0 += __shfl_xor_sync(0xffffffffu, s0, 2);
        s1 += __shfl_xor_sync(0xffffffffu, s1, 1);
        s1 += __shfl_xor_sync(0xffffffffu, s1, 2);
        if ((lane & 3) == 0) {
            int r = rowbase + mi * 16 + (lane >> 2);
            atomicAdd(&g_sumexp[model * TOKENS + r],     s0);
            atomicAdd(&g_sumexp[model * TOKENS + r + 8], s1);
        }
    }
}

// ---------------------------------------------------------------------------
__global__ void k_final(const int* __restrict__ y,
                        const unsigned char* __restrict__ pl_raw,
                        float* __restrict__ out) {
    __shared__ float pol[BATCH], ref[BATCH], cnt[BATCH];
    int tid = threadIdx.x;
    if (tid < BATCH) { pol[tid] = 0.f; ref[tid] = 0.f; cnt[tid] = 0.f; }
    __syncthreads();

    bool y64 = (y[1] == -1);
    for (int m = tid; m < TOKENS; m += blockDim.x) {
        int label = y[y64 ? 2 * m : m];
        if (label >= 0) {
            int b = m / SEQ;
            float p = g_tgt[m]          - logf(g_sumexp[m]);
            float r = g_tgt[TOKENS + m] - logf(g_sumexp[TOKENS + m]);
            atomicAdd(&pol[b], p);
            atomicAdd(&ref[b], r);
            atomicAdd(&cnt[b], 1.f);
        }
    }
    __syncthreads();

    if (tid == 0) {
        // preference_labels dtype hedge: int32 / float32 / byte encodings.
        const uint32_t* pi = (const uint32_t*)pl_raw;
        uint32_t i0 = pi[0], i1 = pi[1], i2 = pi[2], i3 = pi[3];
        bool lab[BATCH];
        bool int_mode = (i0 <= 1u) && (i1 <= 1u) && (i2 <= 1u) && (i3 <= 1u);
        bool flt_mode = !int_mode &&
            (i0 == 0u || i0 == 0x3F800000u) && (i1 == 0u || i1 == 0x3F800000u) &&
            (i2 == 0u || i2 == 0x3F800000u) && (i3 == 0u || i3 == 0x3F800000u);
        if (int_mode) {
            lab[0] = i0 != 0u; lab[1] = i1 != 0u; lab[2] = i2 != 0u; lab[3] = i3 != 0u;
        } else if (flt_mode) {
            lab[0] = i0 != 0u; lab[1] = i1 != 0u; lab[2] = i2 != 0u; lab[3] = i3 != 0u;
        } else {
            #pragma unroll
            for (int b = 0; b < BATCH; b++) lab[b] = pl_raw[b] != 0;
        }

        float loss = 0.f;
        #pragma unroll
        for (int b = 0; b < BATCH; b++) {
            float lp = pol[b] / cnt[b];
            float lr = ref[b] / cnt[b];
            float mult = lab[b] ? 1.f : -1.f;
            float z = 0.1f * (lp - lr) * mult;
            float s = 1.f / (1.f + expf(-z));
            loss += 1.f - s;
        }
        out[0] = loss / (float)BATCH;
    }
}

// ---------------------------------------------------------------------------
extern "C" void kernel_launch(void* const* d_in, const int* in_sizes, int n_in,
                              void* d_out, int out_size) {
    (void)in_sizes; (void)n_in; (void)out_size;
    const float*         x  = (const float*)d_in[0];
    const float*         rx = (const float*)d_in[1];
    const int*           y  = (const int*)d_in[2];
    const unsigned char* pl = (const unsigned char*)d_in[3];
    const float*         W  = (const float*)d_in[4];
    const float*         rW = (const float*)d_in[5];
    float* out = (float*)d_out;

    k_init<<<16, 256>>>();
    k_target<<<(2 * TOKENS * 32) / 256, 256>>>(x, rx, W, rW, y);
    dim3 grid(TOKENS / BM, VOCAB / BN, 2);   // M fastest -> W tile L2 reuse
    k_gemm<<<grid, 256>>>(x, rx, W, rW);
    k_final<<<1, 256>>>(y, pl, out);
}

// round 15
// speedup vs baseline: 1.1039x; 1.1016x over previous
#include <cuda_runtime.h>
#include <cuda_bf16.h>
#include <cstdint>

#define TOKENS 2048   // B*T
#define BATCH  4
#define SEQ    512
#define HID    2048
#define VOCAB  32000

#define BM 128
#define BN 128
#define BK 32
#define LDS_PAD 40    // halves per smem row (32 + 8 pad) -> conflict-free ldmatrix

// scratch (allocation-free rule: __device__ globals)
__device__ float g_sumexp[2 * TOKENS];
__device__ float g_tgt[2 * TOKENS];
// bf16 operand scratch: x/ref_x (8 MB) + W/ref_W (256 MB)
__device__ __nv_bfloat16 g_xb[2][(size_t)TOKENS * HID];
__device__ __nv_bfloat16 g_wb[2][(size_t)VOCAB * HID];

// ---------------------------------------------------------------------------
__global__ void k_init() {
    int i = blockIdx.x * blockDim.x + threadIdx.x;
    if (i < 2 * TOKENS) g_sumexp[i] = 0.f;
}

__device__ __forceinline__ uint2 pack_bf16x4(float4 v) {
    __nv_bfloat162 lo = __floats2bfloat162_rn(v.x, v.y);
    __nv_bfloat162 hi = __floats2bfloat162_rn(v.z, v.w);
    uint2 r;
    r.x = *(uint32_t*)&lo;
    r.y = *(uint32_t*)&hi;
    return r;
}

// fp32 -> bf16 conversion, vectorized, grid-stride (DRAM-bound one-pass)
__global__ void k_cvt(const float4* __restrict__ src, uint2* __restrict__ dst, int n4) {
    int stride = gridDim.x * blockDim.x;
    for (int i = blockIdx.x * blockDim.x + threadIdx.x; i < n4; i += stride)
        dst[i] = pack_bf16x4(src[i]);
}

// ---------------------------------------------------------------------------
// Target logits: one warp per (model, token). Dot(x[m], W[y[m]]) over H=2048.
__global__ void k_target(const float* __restrict__ x, const float* __restrict__ rx,
                         const float* __restrict__ W, const float* __restrict__ rW,
                         const int* __restrict__ y) {
    int warp = (blockIdx.x * blockDim.x + threadIdx.x) >> 5;
    int lane = threadIdx.x & 31;
    if (warp >= 2 * TOKENS) return;
    int model = warp >> 11;            // TOKENS = 2^11
    int m     = warp & (TOKENS - 1);

    // int64-vs-int32 detection: y[0]=y[1]=-100 guaranteed by reference masking.
    bool y64  = (y[1] == -1);
    int label = y[y64 ? 2 * m : m];

    float v = 0.f;
    if (label >= 0) {
        const float4* a4 = (const float4*)((model ? rx : x) + (size_t)m * HID);
        const float4* b4 = (const float4*)((model ? rW : W) + (size_t)label * HID);
        #pragma unroll 4
        for (int i = lane; i < HID / 4; i += 32) {
            float4 av = a4[i], bv = b4[i];
            v += av.x * bv.x + av.y * bv.y + av.z * bv.z + av.w * bv.w;
        }
    }
    #pragma unroll
    for (int s = 16; s; s >>= 1) v += __shfl_xor_sync(0xffffffffu, v, s);
    if (lane == 0) g_tgt[warp] = v;
}

// ---------------------------------------------------------------------------
__device__ __forceinline__ void ldsm_x4(uint32_t& r0, uint32_t& r1, uint32_t& r2,
                                        uint32_t& r3, uint32_t addr) {
    asm volatile("ldmatrix.sync.aligned.m8n8.x4.shared.b16 {%0,%1,%2,%3}, [%4];\n"
                 : "=r"(r0), "=r"(r1), "=r"(r2), "=r"(r3) : "r"(addr));
}
__device__ __forceinline__ void ldsm_x2(uint32_t& r0, uint32_t& r1, uint32_t addr) {
    asm volatile("ldmatrix.sync.aligned.m8n8.x2.shared.b16 {%0,%1}, [%2];\n"
                 : "=r"(r0), "=r"(r1) : "r"(addr));
}
__device__ __forceinline__ void mma16816(float* c, const uint32_t* a, const uint32_t* b) {
    asm volatile(
        "mma.sync.aligned.m16n8k16.row.col.f32.bf16.bf16.f32 "
        "{%0,%1,%2,%3}, {%4,%5,%6,%7}, {%8,%9}, {%0,%1,%2,%3};\n"
        : "+f"(c[0]), "+f"(c[1]), "+f"(c[2]), "+f"(c[3])
        : "r"(a[0]), "r"(a[1]), "r"(a[2]), "r"(a[3]), "r"(b[0]), "r"(b[1]));
}

// GEMM on pre-converted bf16 operands + online exp-sum epilogue.
// grid = (M/BM fastest, N/BN, 2 models); 256 threads = 8 warps in 2(M)x4(N),
// each warp owns a 64x32 output tile via 4x4 m16n8k16 fragments.
__global__ __launch_bounds__(256)
void k_gemm() {
    const int model = blockIdx.z;
    const __nv_bfloat16* A = g_xb[model];
    const __nv_bfloat16* B = g_wb[model];
    const int bm = blockIdx.x;
    const int bn = blockIdx.y;

    __shared__ __nv_bfloat16 As[2][BM * LDS_PAD];
    __shared__ __nv_bfloat16 Bs[2][BN * LDS_PAD];

    const int tid  = threadIdx.x;
    const int lane = tid & 31;
    const int w    = tid >> 5;
    const int wm   = w >> 2;   // 0..1
    const int wn   = w & 3;    // 0..3

    // Global loads: 16B uint4 = 8 halves. A/B tile = 128 rows x 4 chunks.
    // thread t: rows (t>>2) and (t>>2)+64, chunk col (t&3).
    const int glr = tid >> 2;        // 0..63
    const int glc = tid & 3;         // uint4 chunk within the 32-half K-slab
    const __nv_bfloat16* Ag = A + (size_t)(bm * BM + glr) * HID + glc * 8;
    const __nv_bfloat16* Bg = B + (size_t)(bn * BN + glr) * HID + glc * 8;
    const int sA0 = glr * LDS_PAD + glc * 8;
    const int sA1 = sA0 + 64 * LDS_PAD;

    float acc[4][4][4];
    #pragma unroll
    for (int i = 0; i < 4; i++)
        #pragma unroll
        for (int j = 0; j < 4; j++)
            #pragma unroll
            for (int e = 0; e < 4; e++) acc[i][j][e] = 0.f;

    uint32_t asb[2], bsb[2];
    asb[0] = (uint32_t)__cvta_generic_to_shared(&As[0][0]);
    asb[1] = (uint32_t)__cvta_generic_to_shared(&As[1][0]);
    bsb[0] = (uint32_t)__cvta_generic_to_shared(&Bs[0][0]);
    bsb[1] = (uint32_t)__cvta_generic_to_shared(&Bs[1][0]);

    uint4 ra0, ra1, rb0, rb1;
    ra0 = *(const uint4*)(Ag);
    ra1 = *(const uint4*)(Ag + (size_t)64 * HID);
    rb0 = *(const uint4*)(Bg);
    rb1 = *(const uint4*)(Bg + (size_t)64 * HID);
    // stage tile 0 -> buffer 0
    *(uint4*)&As[0][sA0] = ra0;
    *(uint4*)&As[0][sA1] = ra1;
    *(uint4*)&Bs[0][sA0] = rb0;
    *(uint4*)&Bs[0][sA1] = rb1;

    const int KIT = HID / BK;   // 64
    for (int it = 0; it < KIT; ++it) {
        __syncthreads();                       // staged buffer (it&1) visible
        const int buf = it & 1;

        if (it + 1 < KIT) {
            const int ko = (it + 1) * BK;
            ra0 = *(const uint4*)(Ag + ko);
            ra1 = *(const uint4*)(Ag + (size_t)64 * HID + ko);
            rb0 = *(const uint4*)(Bg + ko);
            rb1 = *(const uint4*)(Bg + (size_t)64 * HID + ko);
        }

        #pragma unroll
        for (int ks = 0; ks < 2; ks++) {
            uint32_t af[4][4];
            #pragma unroll
            for (int mi = 0; mi < 4; mi++) {
                int row = wm * 64 + mi * 16 + ((lane >> 3) & 1) * 8 + (lane & 7);
                int col = ks * 16 + (lane >> 4) * 8;
                ldsm_x4(af[mi][0], af[mi][1], af[mi][2], af[mi][3],
                        asb[buf] + (uint32_t)(row * LDS_PAD + col) * 2);
            }
            uint32_t bfrag[4][2];
            #pragma unroll
            for (int ni = 0; ni < 4; ni++) {
                int row = wn * 32 + ni * 8 + (lane & 7);
                int col = ks * 16 + ((lane >> 3) & 1) * 8;
                ldsm_x2(bfrag[ni][0], bfrag[ni][1],
                        bsb[buf] + (uint32_t)(row * LDS_PAD + col) * 2);
            }
            #pragma unroll
            for (int mi = 0; mi < 4; mi++)
                #pragma unroll
                for (int ni = 0; ni < 4; ni++)
                    mma16816(acc[mi][ni], af[mi], bfrag[ni]);
        }

        __syncthreads();                       // everyone done with buf^1 reads
        if (it + 1 < KIT) {
            const int nb = (it + 1) & 1;
            *(uint4*)&As[nb][sA0] = ra0;
            *(uint4*)&As[nb][sA1] = ra1;
            *(uint4*)&Bs[nb][sA0] = rb0;
            *(uint4*)&Bs[nb][sA1] = rb1;
        }
    }

    // Epilogue: exp + row-sum over this block's 128 vocab columns.
    const int rowbase = bm * BM + wm * 64;
    #pragma unroll
    for (int mi = 0; mi < 4; mi++) {
        float s0 = 0.f, s1 = 0.f;
        #pragma unroll
        for (int ni = 0; ni < 4; ni++) {
            s0 += __expf(acc[mi][ni][0]) + __expf(acc[mi][ni][1]);
            s1 += __expf(acc[mi][ni][2]) + __expf(acc[mi][ni][3]);
        }
        s0 += __shfl_xor_sync(0xffffffffu, s0, 1);
        s0 += __shfl_xor_sync(0xffffffffu, s0, 2);
        s1 += __shfl_xor_sync(0xffffffffu, s1, 1);
        s1 += __shfl_xor_sync(0xffffffffu, s1, 2);
        if ((lane & 3) == 0) {
            int r = rowbase + mi * 16 + (lane >> 2);
            atomicAdd(&g_sumexp[model * TOKENS + r],     s0);
            atomicAdd(&g_sumexp[model * TOKENS + r + 8], s1);
        }
    }
}

// ---------------------------------------------------------------------------
// Final reduction: 8 warps, warp w handles batch (w>>1), 256-token half (w&1).
// Per-thread private accumulation + shuffle reduce -> 3 atomics per warp.
__global__ void k_final(const int* __restrict__ y,
                        const unsigned char* __restrict__ pl_raw,
                        float* __restrict__ out) {
    __shared__ float pol[BATCH], ref[BATCH], cnt[BATCH];
    int tid  = threadIdx.x;
    int w    = tid >> 5;
    int lane = tid & 31;
    if (tid < BATCH) { pol[tid] = 0.f; ref[tid] = 0.f; cnt[tid] = 0.f; }
    __syncthreads();

    bool y64 = (y[1] == -1);
    int b    = w >> 1;
    int tok0 = b * SEQ + (w & 1) * 256;
    float sp = 0.f, sr = 0.f, c = 0.f;
    #pragma unroll
    for (int i = lane; i < 256; i += 32) {
        int m = tok0 + i;
        int label = y[y64 ? 2 * m : m];
        if (label >= 0) {
            sp += g_tgt[m]          - __logf(g_sumexp[m]);
            sr += g_tgt[TOKENS + m] - __logf(g_sumexp[TOKENS + m]);
            c  += 1.f;
        }
    }
    #pragma unroll
    for (int s = 16; s; s >>= 1) {
        sp += __shfl_xor_sync(0xffffffffu, sp, s);
        sr += __shfl_xor_sync(0xffffffffu, sr, s);
        c  += __shfl_xor_sync(0xffffffffu, c, s);
    }
    if (lane == 0) {
        atomicAdd(&pol[b], sp);
        atomicAdd(&ref[b], sr);
        atomicAdd(&cnt[b], c);
    }
    __syncthreads();

    if (tid == 0) {
        // preference_labels dtype hedge: int32 / float32 / byte encodings.
        const uint32_t* pi = (const uint32_t*)pl_raw;
        uint32_t i0 = pi[0], i1 = pi[1], i2 = pi[2], i3 = pi[3];
        bool lab[BATCH];
        bool int_mode = (i0 <= 1u) && (i1 <= 1u) && (i2 <= 1u) && (i3 <= 1u);
        bool flt_mode = !int_mode &&
            (i0 == 0u || i0 == 0x3F800000u) && (i1 == 0u || i1 == 0x3F800000u) &&
            (i2 == 0u || i2 == 0x3F800000u) && (i3 == 0u || i3 == 0x3F800000u);
        if (int_mode || flt_mode) {
            lab[0] = i0 != 0u; lab[1] = i1 != 0u; lab[2] = i2 != 0u; lab[3] = i3 != 0u;
        } else {
            #pragma unroll
            for (int bb = 0; bb < BATCH; bb++) lab[bb] = pl_raw[bb] != 0;
        }

        float loss = 0.f;
        #pragma unroll
        for (int bb = 0; bb < BATCH; bb++) {
            float lp = pol[bb] / cnt[bb];
            float lr = ref[bb] / cnt[bb];
            float mult = lab[bb] ? 1.f : -1.f;
            float z = 0.1f * (lp - lr) * mult;
            float s = 1.f / (1.f + expf(-z));
            loss += 1.f - s;
        }
        out[0] = loss / (float)BATCH;
    }
}

// ---------------------------------------------------------------------------
extern "C" void kernel_launch(void* const* d_in, const int* in_sizes, int n_in,
                              void* d_out, int out_size) {
    (void)in_sizes; (void)n_in; (void)out_size;
    const float*         x  = (const float*)d_in[0];
    const float*         rx = (const float*)d_in[1];
    const int*           y  = (const int*)d_in[2];
    const unsigned char* pl = (const unsigned char*)d_in[3];
    const float*         W  = (const float*)d_in[4];
    const float*         rW = (const float*)d_in[5];
    float* out = (float*)d_out;

    k_init<<<16, 256>>>();

    // fp32 -> bf16 pre-conversion (one DRAM pass; halves GEMM L2 traffic)
    __nv_bfloat16* xb  = nullptr; cudaGetSymbolAddress((void**)&xb,  g_xb);
    __nv_bfloat16* wb  = nullptr; cudaGetSymbolAddress((void**)&wb,  g_wb);
    const int n4x = TOKENS * HID / 4;          // 1,048,576
    const int n4w = VOCAB * HID / 4;           // 16,384,000
    k_cvt<<<1024, 256>>>((const float4*)x,  (uint2*)xb, n4x);
    k_cvt<<<1024, 256>>>((const float4*)rx, (uint2*)(xb + (size_t)TOKENS * HID), n4x);
    k_cvt<<<4096, 256>>>((const float4*)W,  (uint2*)wb, n4w);
    k_cvt<<<4096, 256>>>((const float4*)rW, (uint2*)(wb + (size_t)VOCAB * HID), n4w);

    k_target<<<(2 * TOKENS * 32) / 256, 256>>>(x, rx, W, rW, y);
    dim3 grid(TOKENS / BM, VOCAB / BN, 2);   // M fastest -> W tile L2 reuse
    k_gemm<<<grid, 256>>>();
    k_final<<<1, 256>>>(y, pl, out);
}

// round 17
// speedup vs baseline: 1.1734x; 1.0629x over previous
#include <cuda_runtime.h>
#include <cuda_bf16.h>
#include <cstdint>

#define TOKENS 2048   // B*T
#define BATCH  4
#define SEQ    512
#define HID    2048
#define VOCAB  32000

#define BM 128
#define BN 128
#define BK 32
#define LDS_PAD 40            // halves per smem row (32 + 8 pad) -> conflict-free ldmatrix
#define STAGES 4
#define TILE_HALVES (BM * LDS_PAD)        // 5120 halves = 10240 B per operand tile
#define B_BASE (STAGES * TILE_HALVES)     // B tiles start after 4 A tiles
#define SMEM_BYTES (2 * STAGES * TILE_HALVES * 2)   // 81920

// scratch (allocation-free rule: __device__ globals)
__device__ float g_sumexp[2 * TOKENS];
__device__ float g_tgt[2 * TOKENS];
__device__ __nv_bfloat16 g_xb[2][(size_t)TOKENS * HID];
__device__ __nv_bfloat16 g_wb[2][(size_t)VOCAB * HID];

// ---------------------------------------------------------------------------
__device__ __forceinline__ uint32_t smem_u32(const void* p) {
    uint32_t a;
    asm("{ .reg .u64 t; cvta.to.shared.u64 t, %1; cvt.u32.u64 %0, t; }"
        : "=r"(a) : "l"(p));
    return a;
}
__device__ __forceinline__ void cp_async16(uint32_t dst, const void* src) {
    asm volatile("cp.async.cg.shared.global [%0], [%1], 16;\n"
                 :: "r"(dst), "l"(src) : "memory");
}
#define CP_COMMIT() asm volatile("cp.async.commit_group;\n" ::: "memory")
#define CP_WAIT2()  asm volatile("cp.async.wait_group 2;\n" ::: "memory")

__device__ __forceinline__ void ldsm_x4(uint32_t& r0, uint32_t& r1, uint32_t& r2,
                                        uint32_t& r3, uint32_t addr) {
    asm volatile("ldmatrix.sync.aligned.m8n8.x4.shared.b16 {%0,%1,%2,%3}, [%4];\n"
                 : "=r"(r0), "=r"(r1), "=r"(r2), "=r"(r3) : "r"(addr));
}
__device__ __forceinline__ void ldsm_x2(uint32_t& r0, uint32_t& r1, uint32_t addr) {
    asm volatile("ldmatrix.sync.aligned.m8n8.x2.shared.b16 {%0,%1}, [%2];\n"
                 : "=r"(r0), "=r"(r1) : "r"(addr));
}
__device__ __forceinline__ void mma16816(float* c, const uint32_t* a, const uint32_t* b) {
    asm volatile(
        "mma.sync.aligned.m16n8k16.row.col.f32.bf16.bf16.f32 "
        "{%0,%1,%2,%3}, {%4,%5,%6,%7}, {%8,%9}, {%0,%1,%2,%3};\n"
        : "+f"(c[0]), "+f"(c[1]), "+f"(c[2]), "+f"(c[3])
        : "r"(a[0]), "r"(a[1]), "r"(a[2]), "r"(a[3]), "r"(b[0]), "r"(b[1]));
}

// ---------------------------------------------------------------------------
__global__ void k_init() {
    int i = blockIdx.x * blockDim.x + threadIdx.x;
    if (i < 2 * TOKENS) g_sumexp[i] = 0.f;
}

__device__ __forceinline__ uint2 pack_bf16x4(float4 v) {
    __nv_bfloat162 lo = __floats2bfloat162_rn(v.x, v.y);
    __nv_bfloat162 hi = __floats2bfloat162_rn(v.z, v.w);
    uint2 r;
    r.x = *(uint32_t*)&lo;
    r.y = *(uint32_t*)&hi;
    return r;
}

// fp32 -> bf16 conversion, vectorized, grid-stride (83% of DRAM peak measured)
__global__ void k_cvt(const float4* __restrict__ src, uint2* __restrict__ dst, int n4) {
    int stride = gridDim.x * blockDim.x;
    for (int i = blockIdx.x * blockDim.x + threadIdx.x; i < n4; i += stride)
        dst[i] = pack_bf16x4(src[i]);
}

// ---------------------------------------------------------------------------
// Target logits: one warp per (model, token). Dot(x[m], W[y[m]]) over H=2048.
__global__ void k_target(const float* __restrict__ x, const float* __restrict__ rx,
                         const float* __restrict__ W, const float* __restrict__ rW,
                         const int* __restrict__ y) {
    int warp = (blockIdx.x * blockDim.x + threadIdx.x) >> 5;
    int lane = threadIdx.x & 31;
    if (warp >= 2 * TOKENS) return;
    int model = warp >> 11;            // TOKENS = 2^11
    int m     = warp & (TOKENS - 1);

    // int64-vs-int32 detection: y[0]=y[1]=-100 guaranteed by reference masking.
    bool y64  = (y[1] == -1);
    int label = y[y64 ? 2 * m : m];

    float v = 0.f;
    if (label >= 0) {
        const float4* a4 = (const float4*)((model ? rx : x) + (size_t)m * HID);
        const float4* b4 = (const float4*)((model ? rW : W) + (size_t)label * HID);
        #pragma unroll 4
        for (int i = lane; i < HID / 4; i += 32) {
            float4 av = a4[i], bv = b4[i];
            v += av.x * bv.x + av.y * bv.y + av.z * bv.z + av.w * bv.w;
        }
    }
    #pragma unroll
    for (int s = 16; s; s >>= 1) v += __shfl_xor_sync(0xffffffffu, v, s);
    if (lane == 0) g_tgt[warp] = v;
}

// ---------------------------------------------------------------------------
// GEMM on pre-converted bf16 operands, 4-stage cp.async pipeline, mma.sync.
// grid = (M/BM fastest, N/BN, 2 models); 256 threads = 8 warps in 2(M)x4(N),
// each warp owns a 64x32 output tile via 4x4 m16n8k16 fragments (layout proven
// in R14/R15: rel_err 0.0). Epilogue: exp + row-sum -> atomicAdd.
__global__ __launch_bounds__(256, 2)
void k_gemm() {
    extern __shared__ __nv_bfloat16 sm[];
    const uint32_t sb = smem_u32(sm);
    const int model = blockIdx.z;
    const __nv_bfloat16* A = g_xb[model] + (size_t)(blockIdx.x * BM) * HID;
    const __nv_bfloat16* B = g_wb[model] + (size_t)(blockIdx.y * BN) * HID;

    const int tid  = threadIdx.x;
    const int lane = tid & 31;
    const int w    = tid >> 5;
    const int wm   = w >> 2;   // 0..1
    const int wn   = w & 3;    // 0..3

    // cp.async staging: tile = 128 rows x 4 16B-chunks = 512 chunks;
    // 256 threads -> 2 chunks each per operand. addr stride/row = 80 B (16B-mult).
    const int c0r = tid >> 2, c0c = tid & 3;          // chunk tid
    const int c1r = c0r + 64;                         // chunk tid+256
    #define LOAD_SLAB(slab, s)                                                 \
    do {                                                                       \
        const int ko = (slab) * BK;                                            \
        const uint32_t ab = sb + (uint32_t)(s) * (TILE_HALVES * 2);            \
        const uint32_t bb = sb + (uint32_t)(B_BASE + (s) * TILE_HALVES) * 2;   \
        cp_async16(ab + (uint32_t)(c0r * LDS_PAD + c0c * 8) * 2,               \
                   A + (size_t)c0r * HID + ko + c0c * 8);                      \
        cp_async16(ab + (uint32_t)(c1r * LDS_PAD + c0c * 8) * 2,               \
                   A + (size_t)c1r * HID + ko + c0c * 8);                      \
        cp_async16(bb + (uint32_t)(c0r * LDS_PAD + c0c * 8) * 2,               \
                   B + (size_t)c0r * HID + ko + c0c * 8);                      \
        cp_async16(bb + (uint32_t)(c1r * LDS_PAD + c0c * 8) * 2,               \
                   B + (size_t)c1r * HID + ko + c0c * 8);                      \
        CP_COMMIT();                                                           \
    } while (0)

    float acc[4][4][4];
    #pragma unroll
    for (int i = 0; i < 4; i++)
        #pragma unroll
        for (int j = 0; j < 4; j++)
            #pragma unroll
            for (int e = 0; e < 4; e++) acc[i][j][e] = 0.f;

    LOAD_SLAB(0, 0);
    LOAD_SLAB(1, 1);
    LOAD_SLAB(2, 2);

    // ldmatrix per-thread addresses (stage-invariant parts)
    const int arow = wm * 64 + ((lane >> 3) & 1) * 8 + (lane & 7);
    const int acol = (lane >> 4) * 8;
    const int brow = wn * 32 + (lane & 7);
    const int bcol = ((lane >> 3) & 1) * 8;

    const int KIT = HID / BK;   // 64
    for (int it = 0; it < KIT; ++it) {
        const int buf = it & 3;
        CP_WAIT2();                 // stage `it` resident (<=2 groups pending)
        __syncthreads();            // all threads' stage-`it` chunks visible;
                                    // also: slot (it+3)&3 fully consumed @ it-1
        if (it + 3 < KIT) LOAD_SLAB(it + 3, (it + 3) & 3);

        const uint32_t ab = sb + (uint32_t)buf * (TILE_HALVES * 2);
        const uint32_t bb = sb + (uint32_t)(B_BASE + buf * TILE_HALVES) * 2;

        #pragma unroll
        for (int ks = 0; ks < 2; ks++) {
            uint32_t af[4][4];
            #pragma unroll
            for (int mi = 0; mi < 4; mi++) {
                int row = arow + mi * 16;
                int col = ks * 16 + acol;
                ldsm_x4(af[mi][0], af[mi][1], af[mi][2], af[mi][3],
                        ab + (uint32_t)(row * LDS_PAD + col) * 2);
            }
            uint32_t bf[4][2];
            #pragma unroll
            for (int ni = 0; ni < 4; ni++) {
                int row = brow + ni * 8;
                int col = ks * 16 + bcol;
                ldsm_x2(bf[ni][0], bf[ni][1],
                        bb + (uint32_t)(row * LDS_PAD + col) * 2);
            }
            #pragma unroll
            for (int mi = 0; mi < 4; mi++)
                #pragma unroll
                for (int ni = 0; ni < 4; ni++)
                    mma16816(acc[mi][ni], af[mi], bf[ni]);
        }
    }
    #undef LOAD_SLAB

    // Epilogue: exp + row-sum over this block's 128 vocab columns.
    // c0,c1 -> row lane>>2 ; c2,c3 -> row (lane>>2)+8 ; quad lanes share a row.
    const int rowbase = blockIdx.x * BM + wm * 64;
    #pragma unroll
    for (int mi = 0; mi < 4; mi++) {
        float s0 = 0.f, s1 = 0.f;
        #pragma unroll
        for (int ni = 0; ni < 4; ni++) {
            s0 += __expf(acc[mi][ni][0]) + __expf(acc[mi][ni][1]);
            s1 += __expf(acc[mi][ni][2]) + __expf(acc[mi][ni][3]);
        }
        s0 += __shfl_xor_sync(0xffffffffu, s0, 1);
        s0 += __shfl_xor_sync(0xffffffffu, s0, 2);
        s1 += __shfl_xor_sync(0xffffffffu, s1, 1);
        s1 += __shfl_xor_sync(0xffffffffu, s1, 2);
        if ((lane & 3) == 0) {
            int r = rowbase + mi * 16 + (lane >> 2);
            atomicAdd(&g_sumexp[model * TOKENS + r],     s0);
            atomicAdd(&g_sumexp[model * TOKENS + r + 8], s1);
        }
    }
}

// ---------------------------------------------------------------------------
// Final reduction: 8 warps, warp w handles batch (w>>1), 256-token half (w&1).
__global__ void k_final(const int* __restrict__ y,
                        const unsigned char* __restrict__ pl_raw,
                        float* __restrict__ out) {
    __shared__ float pol[BATCH], ref[BATCH], cnt[BATCH];
    int tid  = threadIdx.x;
    int w    = tid >> 5;
    int lane = tid & 31;
    if (tid < BATCH) { pol[tid] = 0.f; ref[tid] = 0.f; cnt[tid] = 0.f; }
    __syncthreads();

    bool y64 = (y[1] == -1);
    int b    = w >> 1;
    int tok0 = b * SEQ + (w & 1) * 256;
    float sp = 0.f, sr = 0.f, c = 0.f;
    #pragma unroll
    for (int i = lane; i < 256; i += 32) {
        int m = tok0 + i;
        int label = y[y64 ? 2 * m : m];
        if (label >= 0) {
            sp += g_tgt[m]          - __logf(g_sumexp[m]);
            sr += g_tgt[TOKENS + m] - __logf(g_sumexp[TOKENS + m]);
            c  += 1.f;
        }
    }
    #pragma unroll
    for (int s = 16; s; s >>= 1) {
        sp += __shfl_xor_sync(0xffffffffu, sp, s);
        sr += __shfl_xor_sync(0xffffffffu, sr, s);
        c  += __shfl_xor_sync(0xffffffffu, c, s);
    }
    if (lane == 0) {
        atomicAdd(&pol[b], sp);
        atomicAdd(&ref[b], sr);
        atomicAdd(&cnt[b], c);
    }
    __syncthreads();

    if (tid == 0) {
        // preference_labels dtype hedge: int32 / float32 / byte encodings.
        const uint32_t* pi = (const uint32_t*)pl_raw;
        uint32_t i0 = pi[0], i1 = pi[1], i2 = pi[2], i3 = pi[3];
        bool lab[BATCH];
        bool int_mode = (i0 <= 1u) && (i1 <= 1u) && (i2 <= 1u) && (i3 <= 1u);
        bool flt_mode = !int_mode &&
            (i0 == 0u || i0 == 0x3F800000u) && (i1 == 0u || i1 == 0x3F800000u) &&
            (i2 == 0u || i2 == 0x3F800000u) && (i3 == 0u || i3 == 0x3F800000u);
        if (int_mode || flt_mode) {
            lab[0] = i0 != 0u; lab[1] = i1 != 0u; lab[2] = i2 != 0u; lab[3] = i3 != 0u;
        } else {
            #pragma unroll
            for (int bb = 0; bb < BATCH; bb++) lab[bb] = pl_raw[bb] != 0;
        }

        float loss = 0.f;
        #pragma unroll
        for (int bb = 0; bb < BATCH; bb++) {
            float lp = pol[bb] / cnt[bb];
            float lr = ref[bb] / cnt[bb];
            float mult = lab[bb] ? 1.f : -1.f;
            float z = 0.1f * (lp - lr) * mult;
            float s = 1.f / (1.f + expf(-z));
            loss += 1.f - s;
        }
        out[0] = loss / (float)BATCH;
    }
}

// ---------------------------------------------------------------------------
extern "C" void kernel_launch(void* const* d_in, const int* in_sizes, int n_in,
                              void* d_out, int out_size) {
    (void)in_sizes; (void)n_in; (void)out_size;
    const float*         x  = (const float*)d_in[0];
    const float*         rx = (const float*)d_in[1];
    const int*           y  = (const int*)d_in[2];
    const unsigned char* pl = (const unsigned char*)d_in[3];
    const float*         W  = (const float*)d_in[4];
    const float*         rW = (const float*)d_in[5];
    float* out = (float*)d_out;

    cudaFuncSetAttribute(k_gemm, cudaFuncAttributeMaxDynamicSharedMemorySize, SMEM_BYTES);

    k_init<<<16, 256>>>();

    // fp32 -> bf16 pre-conversion (one DRAM pass)
    __nv_bfloat16* xb = nullptr; cudaGetSymbolAddress((void**)&xb, g_xb);
    __nv_bfloat16* wb = nullptr; cudaGetSymbolAddress((void**)&wb, g_wb);
    const int n4x = TOKENS * HID / 4;
    const int n4w = VOCAB * HID / 4;
    k_cvt<<<1024, 256>>>((const float4*)x,  (uint2*)xb, n4x);
    k_cvt<<<1024, 256>>>((const float4*)rx, (uint2*)(xb + (size_t)TOKENS * HID), n4x);
    k_cvt<<<4096, 256>>>((const float4*)W,  (uint2*)wb, n4w);
    k_cvt<<<4096, 256>>>((const float4*)rW, (uint2*)(wb + (size_t)VOCAB * HID), n4w);

    k_target<<<(2 * TOKENS * 32) / 256, 256>>>(x, rx, W, rW, y);
    dim3 grid(TOKENS / BM, VOCAB / BN, 2);   // M fastest -> W tile L2 reuse
    k_gemm<<<grid, 256, SMEM_BYTES>>>();
    k_final<<<1, 256>>>(y, pl, out);
}